// round 1
// baseline (speedup 1.0000x reference)
#include <cuda_runtime.h>

// CapsuleLayer dynamic routing, fully fused.
// Shapes: B=64, R=2048, C=16, O=32, I=16. NUM_ROUTING_ITERATIONS=3.
// Grid: one CTA per r (2048 CTAs, 256 threads). Each warp handles 8 b's.
// u_hat kept in registers (f32x2-packed over b-pairs), W[r] staged in smem.

#define FULLM 0xffffffffu

static __device__ __forceinline__ float2 ffma2(float2 a, float2 b, float2 c) {
    unsigned long long ua = *reinterpret_cast<unsigned long long*>(&a);
    unsigned long long ub = *reinterpret_cast<unsigned long long*>(&b);
    unsigned long long uc = *reinterpret_cast<unsigned long long*>(&c);
    unsigned long long ud;
    asm("fma.rn.f32x2 %0, %1, %2, %3;" : "=l"(ud) : "l"(ua), "l"(ub), "l"(uc));
    return *reinterpret_cast<float2*>(&ud);
}

static __device__ __forceinline__ float2 pack2(float x) {
    unsigned long long r;
    asm("mov.b64 %0, {%1, %1};" : "=l"(r) : "f"(x));
    return *reinterpret_cast<float2*>(&r);
}

static __device__ __forceinline__ float rcp_approx(float x) {
    float r; asm("rcp.approx.f32 %0, %1;" : "=f"(r) : "f"(x)); return r;
}
static __device__ __forceinline__ float sqrt_approx(float x) {
    float r; asm("sqrt.approx.f32 %0, %1;" : "=f"(r) : "f"(x)); return r;
}

// Transpose-reduce: given per-lane t[c] = uc[c]*v (c=0..15, lane=o over 32 lanes),
// returns S[lane%16] = sum over all 32 lanes of t[lane%16], replicated on both halves.
// Vector-halving butterfly: 8+4+2+1+1 = 16 shuffles.
static __device__ __forceinline__ float tr16(const float* uc, float v, int lane) {
    const int b0 = lane & 1, b1 = (lane >> 1) & 1, b2 = (lane >> 2) & 1, b3 = (lane >> 3) & 1;
    float a[8];
#pragma unroll
    for (int k = 0; k < 8; k++) {
        float keep = (b0 ? uc[2 * k + 1] : uc[2 * k]) * v;
        float give = (b0 ? uc[2 * k] : uc[2 * k + 1]) * v;
        a[k] = keep + __shfl_xor_sync(FULLM, give, 1);
    }
    float c2[4];
#pragma unroll
    for (int k = 0; k < 4; k++) {
        float keep = b1 ? a[2 * k + 1] : a[2 * k];
        float give = b1 ? a[2 * k] : a[2 * k + 1];
        c2[k] = keep + __shfl_xor_sync(FULLM, give, 2);
    }
    float d0, d1;
    {
        float keep = b2 ? c2[1] : c2[0];
        float give = b2 ? c2[0] : c2[1];
        d0 = keep + __shfl_xor_sync(FULLM, give, 4);
        keep = b2 ? c2[3] : c2[2];
        give = b2 ? c2[2] : c2[3];
        d1 = keep + __shfl_xor_sync(FULLM, give, 4);
    }
    float e;
    {
        float keep = b3 ? d1 : d0;
        float give = b3 ? d0 : d1;
        e = keep + __shfl_xor_sync(FULLM, give, 8);
    }
    e += __shfl_xor_sync(FULLM, e, 16);
    return e;  // = sum_{lanes} uc[lane%16]*v  i.e. dot(u[c= lane%16, :], vvec)
}

__global__ void __launch_bounds__(256, 1)
caps_routing_kernel(const float* __restrict__ x,   // [64, 2048, 16]
                    const float* __restrict__ W,   // [2048, 16, 32, 16]
                    float* __restrict__ out)       // [64, 2048, 32]
{
    const int r = blockIdx.x;
    const int tid = threadIdx.x;
    const int lane = tid & 31;   // = o
    const int wid = tid >> 5;    // warp handles b in [8*wid, 8*wid+8)

    // ---- shared memory ----
    // W staged as [i4][c][o] of float4 (4 consecutive i per element), pad 513 for bank phase.
    __shared__ float4 Ws4[4 * 513];          // 32832 B
    __shared__ float2 Xs[32 * 16];           // Xs[p*16+i] = {x[2p][i], x[2p+1][i]}   4096 B
    __shared__ float  Rbuf[8][16];           // per-warp route broadcast row          512 B

    // ---- stage W[r] (32 KB) with i4-major transpose ----
    {
        const float4* Wg4 = reinterpret_cast<const float4*>(W + (size_t)r * 8192);
#pragma unroll
        for (int k = 0; k < 8; k++) {
            int f = tid + k * 256;           // float4 index within [16c][32o][4 i4]
            float4 v = Wg4[f];
            int c = f >> 7, o = (f >> 2) & 31, i4 = f & 3;
            Ws4[i4 * 513 + c * 32 + o] = v;
        }
    }
    // ---- stage x[:, r, :] packed as b-pairs ----
    {
        int b = tid >> 2, q = tid & 3;
        const float4* xg4 = reinterpret_cast<const float4*>(x + (size_t)b * 32768 + (size_t)r * 16);
        float4 xv = xg4[q];
        int p = b >> 1, par = b & 1;
        float* xsf = reinterpret_cast<float*>(Xs);
        xsf[((p * 16 + q * 4 + 0) << 1) + par] = xv.x;
        xsf[((p * 16 + q * 4 + 1) << 1) + par] = xv.y;
        xsf[((p * 16 + q * 4 + 2) << 1) + par] = xv.z;
        xsf[((p * 16 + q * 4 + 3) << 1) + par] = xv.w;
    }
    __syncthreads();

    // ---- u_hat: u[p][c] = f32x2 over b-pair (b=8*wid+2p, 8*wid+2p+1), lane = o ----
    float2 u[4][16];
#pragma unroll
    for (int p = 0; p < 4; p++)
#pragma unroll
        for (int c = 0; c < 16; c++) u[p][c] = make_float2(0.f, 0.f);

#pragma unroll
    for (int i4 = 0; i4 < 4; i4++) {
        float2 xv[4][4];
#pragma unroll
        for (int p = 0; p < 4; p++) {
            const float4* xp = reinterpret_cast<const float4*>(&Xs[(wid * 4 + p) * 16 + i4 * 4]);
            float4 q0 = xp[0];
            float4 q1 = xp[1];
            xv[p][0] = make_float2(q0.x, q0.y);
            xv[p][1] = make_float2(q0.z, q0.w);
            xv[p][2] = make_float2(q1.x, q1.y);
            xv[p][3] = make_float2(q1.z, q1.w);
        }
#pragma unroll
        for (int c = 0; c < 16; c++) {
            float4 w4 = Ws4[i4 * 513 + c * 32 + lane];
            float2 w0 = pack2(w4.x), w1 = pack2(w4.y), w2 = pack2(w4.z), w3 = pack2(w4.w);
#pragma unroll
            for (int p = 0; p < 4; p++) {
                u[p][c] = ffma2(w0, xv[p][0], u[p][c]);
                u[p][c] = ffma2(w1, xv[p][1], u[p][c]);
                u[p][c] = ffma2(w2, xv[p][2], u[p][c]);
                u[p][c] = ffma2(w3, xv[p][3], u[p][c]);
            }
        }
    }

    // ---- dynamic routing per b (3 iterations; iter1 softmax(0) is uniform,
    //      final b-update is dead -> 2 softmaxes, 2 agreement updates) ----
#pragma unroll
    for (int j = 0; j < 8; j++) {
        const int p = j >> 1;
        float uc[16];
#pragma unroll
        for (int c = 0; c < 16; c++) uc[c] = (j & 1) ? u[p][c].y : u[p][c].x;

        // iteration 1: route = 1/16 uniform
        float s = uc[0];
#pragma unroll
        for (int c = 1; c < 16; c++) s += uc[c];
        s *= 0.0625f;

        float nsq = s * s;
        nsq += __shfl_xor_sync(FULLM, nsq, 16);
        nsq += __shfl_xor_sync(FULLM, nsq, 8);
        nsq += __shfl_xor_sync(FULLM, nsq, 4);
        nsq += __shfl_xor_sync(FULLM, nsq, 2);
        nsq += __shfl_xor_sync(FULLM, nsq, 1);
        float fac = sqrt_approx(nsq) * rcp_approx(1.0f + nsq);
        float v = s * fac;

        float bown = tr16(uc, v, lane);   // b logit for c = lane%16 (replicated halves)

        // iterations 2 and 3
#pragma unroll
        for (int it = 0; it < 2; it++) {
            // distributed softmax over c (b values bounded, skip max-subtraction)
            float e = __expf(bown);
            float Z = e;
            Z += __shfl_xor_sync(FULLM, Z, 1);
            Z += __shfl_xor_sync(FULLM, Z, 2);
            Z += __shfl_xor_sync(FULLM, Z, 4);
            Z += __shfl_xor_sync(FULLM, Z, 8);
            float route = e * rcp_approx(Z);

            // broadcast the 16 route values via smem row
            __syncwarp();
            if (lane < 16) Rbuf[wid][lane] = route;
            __syncwarp();
            const float4* rb4 = reinterpret_cast<const float4*>(Rbuf[wid]);
            float4 r0 = rb4[0], r1 = rb4[1], r2 = rb4[2], r3 = rb4[3];
            float rt[16] = {r0.x, r0.y, r0.z, r0.w, r1.x, r1.y, r1.z, r1.w,
                            r2.x, r2.y, r2.z, r2.w, r3.x, r3.y, r3.z, r3.w};

            s = rt[0] * uc[0];
#pragma unroll
            for (int c = 1; c < 16; c++) s = fmaf(rt[c], uc[c], s);

            nsq = s * s;
            nsq += __shfl_xor_sync(FULLM, nsq, 16);
            nsq += __shfl_xor_sync(FULLM, nsq, 8);
            nsq += __shfl_xor_sync(FULLM, nsq, 4);
            nsq += __shfl_xor_sync(FULLM, nsq, 2);
            nsq += __shfl_xor_sync(FULLM, nsq, 1);
            fac = sqrt_approx(nsq) * rcp_approx(1.0f + nsq);
            v = s * fac;

            if (it == 0) bown += tr16(uc, v, lane);
        }

        // write v for b = 8*wid + j : out[b][r][o]
        const int bg = wid * 8 + j;
        out[(size_t)bg * 65536 + (size_t)r * 32 + lane] = v;
    }
}

extern "C" void kernel_launch(void* const* d_in, const int* in_sizes, int n_in,
                              void* d_out, int out_size) {
    const float* x = (const float*)d_in[0];
    const float* W = (const float*)d_in[1];
    // defensive: x is the smaller input (2,097,152 vs 16,777,216 elements)
    if (n_in >= 2 && in_sizes[0] > in_sizes[1]) {
        const float* t = x; x = W; W = t;
    }
    float* out = (float*)d_out;
    caps_routing_kernel<<<2048, 256>>>(x, W, out);
}

// round 2
// speedup vs baseline: 1.2925x; 1.2925x over previous
#include <cuda_runtime.h>

// CapsuleLayer dynamic routing, fully fused. Round 2: occupancy fix.
// Shapes: B=64, R=2048, C=16, O=32, I=16. 3 routing iterations.
// Grid: one CTA per r (2048 CTAs, 512 threads = 16 warps).
// Each warp handles 4 b's as 2 f32x2 pairs -> 64 accumulator regs.
// Routing executed in f32x2 over each b-pair.

#define FULLM 0xffffffffu

static __device__ __forceinline__ float2 ffma2(float2 a, float2 b, float2 c) {
    unsigned long long ua = *reinterpret_cast<unsigned long long*>(&a);
    unsigned long long ub = *reinterpret_cast<unsigned long long*>(&b);
    unsigned long long uc = *reinterpret_cast<unsigned long long*>(&c);
    unsigned long long ud;
    asm("fma.rn.f32x2 %0, %1, %2, %3;" : "=l"(ud) : "l"(ua), "l"(ub), "l"(uc));
    return *reinterpret_cast<float2*>(&ud);
}
static __device__ __forceinline__ float2 add2(float2 a, float2 b) {
    unsigned long long ua = *reinterpret_cast<unsigned long long*>(&a);
    unsigned long long ub = *reinterpret_cast<unsigned long long*>(&b);
    unsigned long long ud;
    asm("add.rn.f32x2 %0, %1, %2;" : "=l"(ud) : "l"(ua), "l"(ub));
    return *reinterpret_cast<float2*>(&ud);
}
static __device__ __forceinline__ float2 mul2(float2 a, float2 b) {
    unsigned long long ua = *reinterpret_cast<unsigned long long*>(&a);
    unsigned long long ub = *reinterpret_cast<unsigned long long*>(&b);
    unsigned long long ud;
    asm("mul.rn.f32x2 %0, %1, %2;" : "=l"(ud) : "l"(ua), "l"(ub));
    return *reinterpret_cast<float2*>(&ud);
}
static __device__ __forceinline__ float2 pack2(float x) {
    unsigned long long r;
    asm("mov.b64 %0, {%1, %1};" : "=l"(r) : "f"(x));
    return *reinterpret_cast<float2*>(&r);
}
static __device__ __forceinline__ float rcp_approx(float x) {
    float r; asm("rcp.approx.f32 %0, %1;" : "=f"(r) : "f"(x)); return r;
}
static __device__ __forceinline__ float sqrt_approx(float x) {
    float r; asm("sqrt.approx.f32 %0, %1;" : "=f"(r) : "f"(x)); return r;
}
static __device__ __forceinline__ float2 shfl_xor2(float2 v, int m) {
    v.x = __shfl_xor_sync(FULLM, v.x, m);
    v.y = __shfl_xor_sync(FULLM, v.y, m);
    return v;
}

// squash over o (lane dim), f32x2 over the b-pair: v = s * sqrt(|s|^2)/(1+|s|^2)
static __device__ __forceinline__ float2 squash2(float2 s) {
    float2 n = mul2(s, s);
    n = add2(n, shfl_xor2(n, 16));
    n = add2(n, shfl_xor2(n, 8));
    n = add2(n, shfl_xor2(n, 4));
    n = add2(n, shfl_xor2(n, 2));
    n = add2(n, shfl_xor2(n, 1));
    float fx = sqrt_approx(n.x) * rcp_approx(1.0f + n.x);
    float fy = sqrt_approx(n.y) * rcp_approx(1.0f + n.y);
    return mul2(s, make_float2(fx, fy));
}

// Transpose-reduce, f32x2 payload: per lane t[c] = S[c]*v (c=0..15, lane=o),
// returns Sum_{o} S[lane%16][o]*v[o], replicated on both 16-lane halves.
static __device__ __forceinline__ float2 tr16_2(const float2* S, float2 v, int lane) {
    const int b0 = lane & 1, b1 = (lane >> 1) & 1, b2 = (lane >> 2) & 1, b3 = (lane >> 3) & 1;
    float2 a[8];
#pragma unroll
    for (int k = 0; k < 8; k++) {
        float2 keep = mul2(b0 ? S[2 * k + 1] : S[2 * k], v);
        float2 give = mul2(b0 ? S[2 * k] : S[2 * k + 1], v);
        a[k] = add2(keep, shfl_xor2(give, 1));
    }
    float2 c4[4];
#pragma unroll
    for (int k = 0; k < 4; k++) {
        float2 keep = b1 ? a[2 * k + 1] : a[2 * k];
        float2 give = b1 ? a[2 * k] : a[2 * k + 1];
        c4[k] = add2(keep, shfl_xor2(give, 2));
    }
    float2 d0, d1;
    {
        float2 keep = b2 ? c4[1] : c4[0];
        float2 give = b2 ? c4[0] : c4[1];
        d0 = add2(keep, shfl_xor2(give, 4));
        keep = b2 ? c4[3] : c4[2];
        give = b2 ? c4[2] : c4[3];
        d1 = add2(keep, shfl_xor2(give, 4));
    }
    float2 e;
    {
        float2 keep = b3 ? d1 : d0;
        float2 give = b3 ? d0 : d1;
        e = add2(keep, shfl_xor2(give, 8));
    }
    e = add2(e, shfl_xor2(e, 16));
    return e;
}

__global__ void __launch_bounds__(512, 1)
caps_routing_kernel(const float* __restrict__ x,   // [64, 2048, 16]
                    const float* __restrict__ W,   // [2048, 16, 32, 16]
                    float* __restrict__ out)       // [64, 2048, 32]
{
    const int r = blockIdx.x;
    const int tid = threadIdx.x;
    const int lane = tid & 31;   // = o
    const int wid = tid >> 5;    // 0..15, warp handles b in [4*wid, 4*wid+4)

    // ---- shared memory ----
    __shared__ float4 Ws4[4 * 514];          // [i4][c][o] float4, pad 514 -> 32896 B
    __shared__ float2 Xs[32 * 16];           // Xs[p*16+i] = {x[2p][i], x[2p+1][i]}  4096 B
    __shared__ float2 Rbuf[16][16];          // per-warp route broadcast row         2048 B

    // ---- stage W[r] (32 KB) with i4-major transpose ----
    {
        const float4* Wg4 = reinterpret_cast<const float4*>(W + (size_t)r * 8192);
#pragma unroll
        for (int k = 0; k < 4; k++) {
            int f = tid + k * 512;           // float4 index within [16c][32o][4 i4]
            float4 v = Wg4[f];
            int c = f >> 7, o = (f >> 2) & 31, i4 = f & 3;
            Ws4[i4 * 514 + c * 32 + o] = v;
        }
    }
    // ---- stage x[:, r, :] packed as b-pairs ----
    if (tid < 256) {
        int b = tid >> 2, q = tid & 3;
        const float4* xg4 = reinterpret_cast<const float4*>(x + (size_t)b * 32768 + (size_t)r * 16);
        float4 xv = xg4[q];
        int p = b >> 1, par = b & 1;
        float* xsf = reinterpret_cast<float*>(Xs);
        xsf[((p * 16 + q * 4 + 0) << 1) + par] = xv.x;
        xsf[((p * 16 + q * 4 + 1) << 1) + par] = xv.y;
        xsf[((p * 16 + q * 4 + 2) << 1) + par] = xv.z;
        xsf[((p * 16 + q * 4 + 3) << 1) + par] = xv.w;
    }
    __syncthreads();

    // ---- u_hat: u[p][c] = f32x2 over b-pair (b = 4*wid+2p, 4*wid+2p+1), lane = o ----
    float2 u[2][16];
#pragma unroll
    for (int p = 0; p < 2; p++)
#pragma unroll
        for (int c = 0; c < 16; c++) u[p][c] = make_float2(0.f, 0.f);

#pragma unroll
    for (int i4 = 0; i4 < 4; i4++) {
        float2 xv[2][4];
#pragma unroll
        for (int p = 0; p < 2; p++) {
            const float4* xp = reinterpret_cast<const float4*>(&Xs[(wid * 2 + p) * 16 + i4 * 4]);
            float4 q0 = xp[0];
            float4 q1 = xp[1];
            xv[p][0] = make_float2(q0.x, q0.y);
            xv[p][1] = make_float2(q0.z, q0.w);
            xv[p][2] = make_float2(q1.x, q1.y);
            xv[p][3] = make_float2(q1.z, q1.w);
        }
#pragma unroll
        for (int c = 0; c < 16; c++) {
            float4 w4 = Ws4[i4 * 514 + c * 32 + lane];
            float2 w0 = pack2(w4.x), w1 = pack2(w4.y), w2 = pack2(w4.z), w3 = pack2(w4.w);
#pragma unroll
            for (int p = 0; p < 2; p++) {
                u[p][c] = ffma2(w0, xv[p][0], u[p][c]);
                u[p][c] = ffma2(w1, xv[p][1], u[p][c]);
                u[p][c] = ffma2(w2, xv[p][2], u[p][c]);
                u[p][c] = ffma2(w3, xv[p][3], u[p][c]);
            }
        }
    }

    // ---- routing per b-pair, f32x2. Iter1 softmax(0)=uniform; final b-update dead. ----
#pragma unroll
    for (int p = 0; p < 2; p++) {
        const float2* S = u[p];

        // iteration 1: route = 1/16 uniform
        float2 s01 = add2(S[0], S[1]),   s23 = add2(S[2], S[3]);
        float2 s45 = add2(S[4], S[5]),   s67 = add2(S[6], S[7]);
        float2 s89 = add2(S[8], S[9]),   sab = add2(S[10], S[11]);
        float2 scd = add2(S[12], S[13]), sef = add2(S[14], S[15]);
        float2 s = add2(add2(add2(s01, s23), add2(s45, s67)),
                        add2(add2(s89, sab), add2(scd, sef)));
        s = mul2(s, make_float2(0.0625f, 0.0625f));

        float2 v = squash2(s);
        float2 bown = tr16_2(S, v, lane);   // routing logit for c = lane%16 (both halves)

#pragma unroll
        for (int it = 0; it < 2; it++) {
            // distributed softmax over c (b bounded, skip max-subtraction)
            float2 e2 = make_float2(__expf(bown.x), __expf(bown.y));
            float2 Z = e2;
            Z = add2(Z, shfl_xor2(Z, 1));
            Z = add2(Z, shfl_xor2(Z, 2));
            Z = add2(Z, shfl_xor2(Z, 4));
            Z = add2(Z, shfl_xor2(Z, 8));
            float2 route = mul2(e2, make_float2(rcp_approx(Z.x), rcp_approx(Z.y)));

            __syncwarp();
            if (lane < 16) Rbuf[wid][lane] = route;
            __syncwarp();

            // s = sum_c route[c] * u[c], routes read via uniform float4 broadcasts
            const float4* rb = reinterpret_cast<const float4*>(&Rbuf[wid][0]);
            float2 sa = make_float2(0.f, 0.f), sb = make_float2(0.f, 0.f);
#pragma unroll
            for (int q = 0; q < 8; q += 2) {
                float4 t0 = rb[q];
                float4 t1 = rb[q + 1];
                sa = ffma2(make_float2(t0.x, t0.y), S[2 * q + 0], sa);
                sb = ffma2(make_float2(t0.z, t0.w), S[2 * q + 1], sb);
                sa = ffma2(make_float2(t1.x, t1.y), S[2 * q + 2], sa);
                sb = ffma2(make_float2(t1.z, t1.w), S[2 * q + 3], sb);
            }
            s = add2(sa, sb);

            v = squash2(s);
            if (it == 0) bown = add2(bown, tr16_2(S, v, lane));
        }

        // write v for b-pair (4*wid + 2p, +1): out[b][r][o]
        const int bg = wid * 4 + 2 * p;
        out[(size_t)bg * 65536 + (size_t)r * 32 + lane] = v.x;
        out[(size_t)(bg + 1) * 65536 + (size_t)r * 32 + lane] = v.y;
    }
}

extern "C" void kernel_launch(void* const* d_in, const int* in_sizes, int n_in,
                              void* d_out, int out_size) {
    const float* x = (const float*)d_in[0];
    const float* W = (const float*)d_in[1];
    // defensive: x is the smaller input (2,097,152 vs 16,777,216 elements)
    if (n_in >= 2 && in_sizes[0] > in_sizes[1]) {
        const float* t = x; x = W; W = t;
    }
    float* out = (float*)d_out;
    caps_routing_kernel<<<2048, 512>>>(x, W, out);
}

// round 3
// speedup vs baseline: 1.3224x; 1.0232x over previous
#include <cuda_runtime.h>

// CapsuleLayer dynamic routing, fully fused. Round 3: 2 CTAs/SM phase overlap.
// Shapes: B=64, R=2048, C=16, O=32, I=16. 3 routing iterations.
// Grid: (2048, 2). CTA = 256 threads = 8 warps, owns 32 b's (blockIdx.y half).
// Warp handles 4 b's as 2 f32x2 pairs. regs capped at 128 -> 2 CTAs resident/SM,
// so one CTA's latency-bound routing overlaps the other's fma-bound GEMM.

#define FULLM 0xffffffffu

static __device__ __forceinline__ float2 ffma2(float2 a, float2 b, float2 c) {
    unsigned long long ua = *reinterpret_cast<unsigned long long*>(&a);
    unsigned long long ub = *reinterpret_cast<unsigned long long*>(&b);
    unsigned long long uc = *reinterpret_cast<unsigned long long*>(&c);
    unsigned long long ud;
    asm("fma.rn.f32x2 %0, %1, %2, %3;" : "=l"(ud) : "l"(ua), "l"(ub), "l"(uc));
    return *reinterpret_cast<float2*>(&ud);
}
static __device__ __forceinline__ float2 add2(float2 a, float2 b) {
    unsigned long long ua = *reinterpret_cast<unsigned long long*>(&a);
    unsigned long long ub = *reinterpret_cast<unsigned long long*>(&b);
    unsigned long long ud;
    asm("add.rn.f32x2 %0, %1, %2;" : "=l"(ud) : "l"(ua), "l"(ub));
    return *reinterpret_cast<float2*>(&ud);
}
static __device__ __forceinline__ float2 mul2(float2 a, float2 b) {
    unsigned long long ua = *reinterpret_cast<unsigned long long*>(&a);
    unsigned long long ub = *reinterpret_cast<unsigned long long*>(&b);
    unsigned long long ud;
    asm("mul.rn.f32x2 %0, %1, %2;" : "=l"(ud) : "l"(ua), "l"(ub));
    return *reinterpret_cast<float2*>(&ud);
}
static __device__ __forceinline__ float2 pack2(float x) {
    unsigned long long r;
    asm("mov.b64 %0, {%1, %1};" : "=l"(r) : "f"(x));
    return *reinterpret_cast<float2*>(&r);
}
static __device__ __forceinline__ float rcp_approx(float x) {
    float r; asm("rcp.approx.f32 %0, %1;" : "=f"(r) : "f"(x)); return r;
}
static __device__ __forceinline__ float sqrt_approx(float x) {
    float r; asm("sqrt.approx.f32 %0, %1;" : "=f"(r) : "f"(x)); return r;
}
static __device__ __forceinline__ float2 shfl_xor2(float2 v, int m) {
    v.x = __shfl_xor_sync(FULLM, v.x, m);
    v.y = __shfl_xor_sync(FULLM, v.y, m);
    return v;
}

// squash over o (lane dim), f32x2 over the b-pair: v = s * sqrt(|s|^2)/(1+|s|^2)
static __device__ __forceinline__ float2 squash2(float2 s) {
    float2 n = mul2(s, s);
    n = add2(n, shfl_xor2(n, 16));
    n = add2(n, shfl_xor2(n, 8));
    n = add2(n, shfl_xor2(n, 4));
    n = add2(n, shfl_xor2(n, 2));
    n = add2(n, shfl_xor2(n, 1));
    float fx = sqrt_approx(n.x) * rcp_approx(1.0f + n.x);
    float fy = sqrt_approx(n.y) * rcp_approx(1.0f + n.y);
    return mul2(s, make_float2(fx, fy));
}

// Transpose-reduce, f32x2 payload: returns Sum_o S[lane%16][o]*v[o],
// replicated on both 16-lane halves. 16 shfl_xor2 (32 SHFL).
static __device__ __forceinline__ float2 tr16_2(const float2* S, float2 v, int lane) {
    const int b0 = lane & 1, b1 = (lane >> 1) & 1, b2 = (lane >> 2) & 1, b3 = (lane >> 3) & 1;
    float2 a[8];
#pragma unroll
    for (int k = 0; k < 8; k++) {
        float2 keep = mul2(b0 ? S[2 * k + 1] : S[2 * k], v);
        float2 give = mul2(b0 ? S[2 * k] : S[2 * k + 1], v);
        a[k] = add2(keep, shfl_xor2(give, 1));
    }
    float2 c4[4];
#pragma unroll
    for (int k = 0; k < 4; k++) {
        float2 keep = b1 ? a[2 * k + 1] : a[2 * k];
        float2 give = b1 ? a[2 * k] : a[2 * k + 1];
        c4[k] = add2(keep, shfl_xor2(give, 2));
    }
    float2 d0, d1;
    {
        float2 keep = b2 ? c4[1] : c4[0];
        float2 give = b2 ? c4[0] : c4[1];
        d0 = add2(keep, shfl_xor2(give, 4));
        keep = b2 ? c4[3] : c4[2];
        give = b2 ? c4[2] : c4[3];
        d1 = add2(keep, shfl_xor2(give, 4));
    }
    float2 e;
    {
        float2 keep = b3 ? d1 : d0;
        float2 give = b3 ? d0 : d1;
        e = add2(keep, shfl_xor2(give, 8));
    }
    e = add2(e, shfl_xor2(e, 16));
    return e;
}

__global__ void __launch_bounds__(256, 2)
caps_routing_kernel(const float* __restrict__ x,   // [64, 2048, 16]
                    const float* __restrict__ W,   // [2048, 16, 32, 16]
                    float* __restrict__ out)       // [64, 2048, 32]
{
    const int r = blockIdx.x;
    const int b_base = blockIdx.y << 5;   // 0 or 32
    const int tid = threadIdx.x;
    const int lane = tid & 31;   // = o
    const int wid = tid >> 5;    // 0..7, warp handles b = b_base + 4*wid + {0..3}

    // ---- shared memory (~36 KB; 2 CTAs -> 72 KB/SM) ----
    __shared__ float4 Ws4[4 * 514];          // [i4][c][o] float4, padded
    __shared__ float2 Xs[16 * 16];           // Xs[p*16+i] = {x[2p][i], x[2p+1][i]} for local pairs
    __shared__ float2 Rbuf[8][16];           // per-warp route broadcast row

    // ---- stage W[r] (32 KB) with i4-major transpose ----
    {
        const float4* Wg4 = reinterpret_cast<const float4*>(W + (size_t)r * 8192);
#pragma unroll
        for (int k = 0; k < 8; k++) {
            int f = tid + k * 256;           // float4 index within [16c][32o][4 i4]
            float4 v = Wg4[f];
            int c = f >> 7, o = (f >> 2) & 31, i4 = f & 3;
            Ws4[i4 * 514 + c * 32 + o] = v;
        }
    }
    // ---- stage x[b_base : b_base+32, r, :] packed as b-pairs ----
    if (tid < 128) {
        int b_loc = tid >> 2, q = tid & 3;
        const float4* xg4 = reinterpret_cast<const float4*>(
            x + (size_t)(b_base + b_loc) * 32768 + (size_t)r * 16);
        float4 xv = xg4[q];
        int p = b_loc >> 1, par = b_loc & 1;
        float* xsf = reinterpret_cast<float*>(Xs);
        xsf[((p * 16 + q * 4 + 0) << 1) + par] = xv.x;
        xsf[((p * 16 + q * 4 + 1) << 1) + par] = xv.y;
        xsf[((p * 16 + q * 4 + 2) << 1) + par] = xv.z;
        xsf[((p * 16 + q * 4 + 3) << 1) + par] = xv.w;
    }
    __syncthreads();

    // ---- u_hat: u[p][c] = f32x2 over local b-pair (wid*2+p), lane = o ----
    float2 u[2][16];
#pragma unroll
    for (int p = 0; p < 2; p++)
#pragma unroll
        for (int c = 0; c < 16; c++) u[p][c] = make_float2(0.f, 0.f);

#pragma unroll
    for (int i4 = 0; i4 < 4; i4++) {
        float2 xv[2][4];
#pragma unroll
        for (int p = 0; p < 2; p++) {
            const float4* xp = reinterpret_cast<const float4*>(&Xs[(wid * 2 + p) * 16 + i4 * 4]);
            float4 q0 = xp[0];   // uniform (broadcast) LDS.128
            float4 q1 = xp[1];
            xv[p][0] = make_float2(q0.x, q0.y);
            xv[p][1] = make_float2(q0.z, q0.w);
            xv[p][2] = make_float2(q1.x, q1.y);
            xv[p][3] = make_float2(q1.z, q1.w);
        }
#pragma unroll
        for (int c = 0; c < 16; c++) {
            float4 w4 = Ws4[i4 * 514 + c * 32 + lane];
            float2 w0 = pack2(w4.x), w1 = pack2(w4.y), w2 = pack2(w4.z), w3 = pack2(w4.w);
#pragma unroll
            for (int p = 0; p < 2; p++) {
                u[p][c] = ffma2(w0, xv[p][0], u[p][c]);
                u[p][c] = ffma2(w1, xv[p][1], u[p][c]);
                u[p][c] = ffma2(w2, xv[p][2], u[p][c]);
                u[p][c] = ffma2(w3, xv[p][3], u[p][c]);
            }
        }
    }

    // ---- routing per b-pair, f32x2. Iter1 softmax(0)=uniform; final b-update dead. ----
#pragma unroll
    for (int p = 0; p < 2; p++) {
        const float2* S = u[p];

        // iteration 1: route = 1/16 uniform
        float2 s01 = add2(S[0], S[1]),   s23 = add2(S[2], S[3]);
        float2 s45 = add2(S[4], S[5]),   s67 = add2(S[6], S[7]);
        float2 s89 = add2(S[8], S[9]),   sab = add2(S[10], S[11]);
        float2 scd = add2(S[12], S[13]), sef = add2(S[14], S[15]);
        float2 s = add2(add2(add2(s01, s23), add2(s45, s67)),
                        add2(add2(s89, sab), add2(scd, sef)));
        s = mul2(s, make_float2(0.0625f, 0.0625f));

        float2 v = squash2(s);
        float2 bown = tr16_2(S, v, lane);   // routing logit for c = lane%16 (both halves)

#pragma unroll
        for (int it = 0; it < 2; it++) {
            // distributed softmax over c (b bounded, skip max-subtraction)
            float2 e2 = make_float2(__expf(bown.x), __expf(bown.y));
            float2 Z = e2;
            Z = add2(Z, shfl_xor2(Z, 1));
            Z = add2(Z, shfl_xor2(Z, 2));
            Z = add2(Z, shfl_xor2(Z, 4));
            Z = add2(Z, shfl_xor2(Z, 8));
            float2 route = mul2(e2, make_float2(rcp_approx(Z.x), rcp_approx(Z.y)));

            __syncwarp();
            if (lane < 16) Rbuf[wid][lane] = route;
            __syncwarp();

            // s = sum_c route[c] * u[c]; routes via uniform float4 broadcasts
            const float4* rb = reinterpret_cast<const float4*>(&Rbuf[wid][0]);
            float2 sa = make_float2(0.f, 0.f), sb = make_float2(0.f, 0.f);
#pragma unroll
            for (int q = 0; q < 8; q += 2) {
                float4 t0 = rb[q];
                float4 t1 = rb[q + 1];
                sa = ffma2(make_float2(t0.x, t0.y), S[2 * q + 0], sa);
                sb = ffma2(make_float2(t0.z, t0.w), S[2 * q + 1], sb);
                sa = ffma2(make_float2(t1.x, t1.y), S[2 * q + 2], sa);
                sb = ffma2(make_float2(t1.z, t1.w), S[2 * q + 3], sb);
            }
            s = add2(sa, sb);

            v = squash2(s);
            if (it == 0) bown = add2(bown, tr16_2(S, v, lane));
        }

        // write v for b-pair: out[b][r][o]
        const int bg = b_base + wid * 4 + 2 * p;
        out[(size_t)bg * 65536 + (size_t)r * 32 + lane] = v.x;
        out[(size_t)(bg + 1) * 65536 + (size_t)r * 32 + lane] = v.y;
    }
}

extern "C" void kernel_launch(void* const* d_in, const int* in_sizes, int n_in,
                              void* d_out, int out_size) {
    const float* x = (const float*)d_in[0];
    const float* W = (const float*)d_in[1];
    // defensive: x is the smaller input (2,097,152 vs 16,777,216 elements)
    if (n_in >= 2 && in_sizes[0] > in_sizes[1]) {
        const float* t = x; x = W; W = t;
    }
    float* out = (float*)d_out;
    dim3 grid(2048, 2);
    caps_routing_kernel<<<grid, 256>>>(x, W, out);
}